// round 6
// baseline (speedup 1.0000x reference)
#include <cuda_runtime.h>

// Problem constants
#define NPIX   65536          // 256*256
#define DH     64             // histogram bins
#define PB     16             // pixels staged per round
#define NCHUNK 18             // pixel chunks per (img,b) -> 16*18 = 288 CTAs (2/SM)
#define CPX    ((NPIX + NCHUNK - 1) / NCHUNK)
#define HISTN  (2 * 8 * 3 * DH * DH)

// Scratch (allocation-free rule: __device__ globals)
__device__ float g_hist[HISTN];   // [img][b][ch][64][64]
__device__ float g_hn[8];

__device__ __forceinline__ float frcp(float x) {
    float r; asm("rcp.approx.f32 %0, %1;" : "=f"(r) : "f"(x)); return r;
}
__device__ __forceinline__ float fsqrt_ap(float x) {
    float r; asm("sqrt.approx.f32 %0, %1;" : "=f"(r) : "f"(x)); return r;
}
__device__ __forceinline__ float plo(unsigned long long v) {
    return __uint_as_float((unsigned int)(v & 0xffffffffull));
}
__device__ __forceinline__ float phi(unsigned long long v) {
    return __uint_as_float((unsigned int)(v >> 32));
}

#define FFMA2(acc, a, b) asm("fma.rn.f32x2 %0, %1, %2, %0;" : "+l"(acc) : "l"(a), "l"(b))

// ---------------------------------------------------------------------------
// Kernel 0: zero a slice of the histogram scratch (3 launches keep hist_kernel
// at global launch index 5 for the ncu -s 5 -c 1 capture).
// ---------------------------------------------------------------------------
__global__ void zero_kernel(int off) {
    int i = off + blockIdx.x * blockDim.x + threadIdx.x;
    if (i < HISTN) g_hist[i] = 0.0f;
}

// ---------------------------------------------------------------------------
// Kernel 1: histogram accumulation.
// 256-thread CTAs, 2 CTAs/SM. Warp w (0..7) owns rows {8w..8w+7}; lane l owns
// col pair {2l, 2l+1}. Row operands are WARP-UNIFORM -> broadcast LDS (N=1,
// 1 cyc/wavefront) which cuts crossbar demand ~2x vs the per-lane tiling.
// 24 packed f32x2 accumulators/thread (8 rows x 1 col-pair x 3 channels).
//
// With U = iy*rbf(ur), Vi = iy*rbf(vr), V = rbf(vr), W = rbf(lg-lb):
//   accR[r][c] = sum U[r]*V[c]  = hist_r[r][c]
//   accG[r][c] = sum U[r]*W[c]  = hist_g[63-r][c]     (reverse rows at writeout)
//   accB[r][c] = sum Vi[r]*W[c] = hist_b[63-r][63-c]  (reverse both at writeout)
//
// Single __syncthreads per 16-pixel round (double-buffered SMEM; Stage B fills
// buf[nxt] while Stage C consumes buf[cur]; pixel scalars broadcast in-warp).
// ---------------------------------------------------------------------------
__global__ void __launch_bounds__(256, 2)
hist_kernel(const float* __restrict__ x, const float* __restrict__ y) {
    int combo = blockIdx.x / NCHUNK;
    int chunk = blockIdx.x % NCHUNK;
    int img = combo >> 3;
    int b   = combo & 7;
    const float* src = img ? y : x;
    const float* pr  = src + (size_t)(b * 3 + 0) * NPIX;
    const float* pg  = src + (size_t)(b * 3 + 1) * NPIX;
    const float* pbl = src + (size_t)(b * 3 + 2) * NPIX;

    int cs = chunk * CPX;
    int ce = cs + CPX; if (ce > NPIX) ce = NPIX;

    // Double-buffered SMEM. "2" arrays hold each value DUPLICATED (f32x2 pairs).
    __shared__ float s_su2 [2][PB][128];  // U  = iy*rbf(ur), duplicated
    __shared__ float s_svi2[2][PB][128];  // Vi = iy*rbf(vr), duplicated
    __shared__ float s_sv  [2][PB][64];   // V  = rbf(vr), natural
    __shared__ float s_w   [2][PB][64];   // W  = rbf(lg-lb), natural

    const int tid = threadIdx.x;
    const int w   = tid >> 5;          // warp 0..7 -> rows 8w..8w+7
    const int l   = tid & 31;          // lane -> cols 2l, 2l+1
    const int p   = tid >> 4;          // pixel-in-round this thread evaluates (Stage B)
    const int i0  = tid & 15;          // bin base (bins i0, i0+16, i0+32, i0+48)
    const bool owner = (i0 == 0);
    const int srcln  = l & 16;         // owner lane within warp (0 or 16)

    unsigned long long accR[8], accG[8], accB[8];
#pragma unroll
    for (int k = 0; k < 8; k++) { accR[k] = 0ull; accG[k] = 0ull; accB[k] = 0ull; }

    const int nr = (ce - cs + PB - 1) / PB;

    // Owner-lane prefetch registers; fr = -1 marks an invalid (pad) pixel.
    int pn = cs + p;
    float fr = -1.f, fg = 0.f, fb = 0.f;
    if (owner && pn < ce) { fr = pr[pn]; fg = pg[pn]; fb = pbl[pn]; }

    // Stage B: evaluate RBF rows for this thread's pixel into buffer nb.
    auto stageB = [&](int nb) {
        float r0 = __shfl_sync(0xffffffffu, fr, srcln);
        float g0 = __shfl_sync(0xffffffffu, fg, srcln);
        float b0 = __shfl_sync(0xffffffffu, fb, srcln);
        bool valid = (r0 >= 0.f);
        float r  = valid ? r0 + 1e-6f : 1.0f;
        float g  = valid ? g0 + 1e-6f : 1.0f;
        float bb = valid ? b0 + 1e-6f : 1.0f;
        float lr = __logf(r), lg = __logf(g), lb = __logf(bb);
        float ur = lr - lg;
        float vr = lr - lb;
        float wv = lg - lb;
        float iy = valid ? fsqrt_ap(fmaf(r, r, fmaf(g, g, bb * bb))) : 0.f;
#pragma unroll
        for (int k = 0; k < 4; k++) {
            int i = i0 + 16 * k;
            float c50 = fmaf((float)i, 300.0f / 63.0f, -150.0f);  // 50 * center_i
            float tu = fmaf(ur, 50.0f, -c50);
            float su = iy * frcp(fmaf(tu, tu, 1.0f));             // U
            float tv = fmaf(vr, 50.0f, -c50);
            float sv = frcp(fmaf(tv, tv, 1.0f));                  // V
            float tw = fmaf(wv, 50.0f, -c50);
            float sw = frcp(fmaf(tw, tw, 1.0f));                  // W
            s_sv[nb][p][i] = sv;
            s_w [nb][p][i] = sw;
            *(float2*)&s_su2 [nb][p][2 * i] = make_float2(su, su);
            float vi = iy * sv;
            *(float2*)&s_svi2[nb][p][2 * i] = make_float2(vi, vi);  // Vi
        }
    };

    // Prologue: fill buffer 0, prefetch round 1.
    stageB(0);
    pn += PB; fr = -1.f;
    if (owner && pn < ce) { fr = pr[pn]; fg = pg[pn]; fb = pbl[pn]; }
    __syncthreads();

    // Warp-uniform row bases (16 floats per warp per pixel = rows 8w..8w+7 dup)
    const float* su2b  = &s_su2 [0][0][0] + 16 * w;
    const float* svi2b = &s_svi2[0][0][0] + 16 * w;
    const float* svb   = &s_sv  [0][0][0] + 2 * l;
    const float* wb    = &s_w   [0][0][0] + 2 * l;

    for (int it = 0; it < nr; it++) {
        int cur = it & 1;
        if (it + 1 < nr) {
            stageB(cur ^ 1);
            pn += PB; fr = -1.f;
            if (owner && pn < ce) { fr = pr[pn]; fg = pg[pn]; fb = pbl[pn]; }
        }

        const float* su2p  = su2b  + cur * (PB * 128);
        const float* svi2p = svi2b + cur * (PB * 128);
        const float* svp   = svb   + cur * (PB * 64);
        const float* wp    = wb    + cur * (PB * 64);

        // Stage C: 16 pixels; uniform row loads (broadcast) + per-lane col pairs.
#pragma unroll
        for (int q = 0; q < PB; q++) {
            ulonglong2 u01 = *(const ulonglong2*)(su2p  + q * 128);       // rows 8w,8w+1 (dup)
            ulonglong2 u23 = *(const ulonglong2*)(su2p  + q * 128 + 4);
            ulonglong2 u45 = *(const ulonglong2*)(su2p  + q * 128 + 8);
            ulonglong2 u67 = *(const ulonglong2*)(su2p  + q * 128 + 12);
            ulonglong2 x01 = *(const ulonglong2*)(svi2p + q * 128);
            ulonglong2 x23 = *(const ulonglong2*)(svi2p + q * 128 + 4);
            ulonglong2 x45 = *(const ulonglong2*)(svi2p + q * 128 + 8);
            ulonglong2 x67 = *(const ulonglong2*)(svi2p + q * 128 + 12);
            unsigned long long cv = *(const unsigned long long*)(svp + q * 64);  // cols 2l,2l+1
            unsigned long long cw = *(const unsigned long long*)(wp  + q * 64);

            unsigned long long rU [8] = { u01.x, u01.y, u23.x, u23.y, u45.x, u45.y, u67.x, u67.y };
            unsigned long long rVi[8] = { x01.x, x01.y, x23.x, x23.y, x45.x, x45.y, x67.x, x67.y };

#pragma unroll
            for (int k = 0; k < 8; k++) {
                FFMA2(accR[k], rU[k],  cv);
                FFMA2(accG[k], rU[k],  cw);
                FFMA2(accB[k], rVi[k], cw);
            }
        }
        __syncthreads();
    }

    // ---- Writeout: atomic reduce into global hist (reversals applied here) ----
    size_t basec = ((size_t)(img * 8 + b)) * 3 * 4096;
    float* hR = g_hist + basec;
    float* hG = g_hist + basec + 4096;
    float* hB = g_hist + basec + 8192;
    int c0 = 2 * l;
#pragma unroll
    for (int k = 0; k < 8; k++) {
        int row  = 8 * w + k;
        int rofw = row * 64;              // forward row offset (R)
        int rofr = (63 - row) * 64;       // reversed row offset (G, B)
        atomicAdd(hR + rofw + c0,      plo(accR[k]));
        atomicAdd(hR + rofw + c0 + 1,  phi(accR[k]));
        atomicAdd(hG + rofr + c0,      plo(accG[k]));
        atomicAdd(hG + rofr + c0 + 1,  phi(accG[k]));
        atomicAdd(hB + rofr + 63 - c0, plo(accB[k]));
        atomicAdd(hB + rofr + 62 - c0, phi(accB[k]));
    }
}

// ---------------------------------------------------------------------------
// Kernel 2: per-batch normalize + Hellinger-style distance
// ---------------------------------------------------------------------------
__global__ void loss_kernel() {
    int b = blockIdx.x;                     // 0..7
    const float* hx = g_hist + (size_t)b * 12288;         // img 0
    const float* hy = g_hist + (size_t)(8 + b) * 12288;   // img 1
    __shared__ float red[256];
    int tid = threadIdx.x;

    float sx = 0.f, sy = 0.f;
    for (int i = tid; i < 12288; i += 256) { sx += hx[i]; sy += hy[i]; }

    red[tid] = sx; __syncthreads();
    for (int s = 128; s > 0; s >>= 1) { if (tid < s) red[tid] += red[tid + s]; __syncthreads(); }
    float Tx = red[0]; __syncthreads();

    red[tid] = sy; __syncthreads();
    for (int s = 128; s > 0; s >>= 1) { if (tid < s) red[tid] += red[tid + s]; __syncthreads(); }
    float Ty = red[0]; __syncthreads();

    float ivx = 1.0f / Tx, ivy = 1.0f / Ty;
    float acc = 0.f;
    for (int i = tid; i < 12288; i += 256) {
        float d = sqrtf(hy[i] * ivy) - sqrtf(hx[i] * ivx);
        acc = fmaf(d, d, acc);
    }
    red[tid] = acc; __syncthreads();
    for (int s = 128; s > 0; s >>= 1) { if (tid < s) red[tid] += red[tid + s]; __syncthreads(); }
    if (tid == 0) g_hn[b] = sqrtf(red[0] * 0.5f);
}

// ---------------------------------------------------------------------------
// Kernel 3: mean over batch
// ---------------------------------------------------------------------------
__global__ void final_kernel(float* out) {
    if (threadIdx.x == 0) {
        float s = 0.f;
#pragma unroll
        for (int i = 0; i < 8; i++) s += g_hn[i];
        out[0] = s * 0.125f;
    }
}

// ---------------------------------------------------------------------------
extern "C" void kernel_launch(void* const* d_in, const int* in_sizes, int n_in,
                              void* d_out, int out_size) {
    const float* x = (const float*)d_in[0];
    const float* y = (const float*)d_in[1];

    const int SLICE = (HISTN + 2) / 3;
    zero_kernel<<<(SLICE + 255) / 256, 256>>>(0);
    zero_kernel<<<(SLICE + 255) / 256, 256>>>(SLICE);
    zero_kernel<<<(SLICE + 255) / 256, 256>>>(2 * SLICE);
    hist_kernel<<<16 * NCHUNK, 256>>>(x, y);
    loss_kernel<<<8, 256>>>();
    final_kernel<<<1, 32>>>((float*)d_out);
}